// round 8
// baseline (speedup 1.0000x reference)
#include <cuda_runtime.h>
#include <cstdint>

// NCC via legacy tensor-core implicit GEMM (mma.sync m16n8k8 tf32, sm_80 PTX).
// Per input row yin, x-strip of 128:
//   D[m, n] = sum_k in(yin, x0+m+k) * W(n, k)    (M=128, N=24, K=24)
// W rows 0..20 = z-normalized template rows, row 21 = ones (free hsum),
// rows 22..23 = zero pad. out(y, x) = sum_i D_yin[x, i], y = yin - i,
// accumulated in a per-thread smem ring (depth 21), quad-shfl reduced.
// 3-term tf32 split (rna): Ah*Bh + Al*Bh + Ah*Bl -> ~1e-6 rel err.
// R8 fixes vs R7: prefetch slot (pr-ys)%NBUF; barrier between finalize and
// GEMM (hs/hq WAR race); ring guard i0 <= yin-ys (warm-up pollution).

#define EPSF   1e-8f
#define TH     21
#define PLANES 48
#define H      512
#define W      512
#define OH     492
#define OW     492
#define XS     128
#define YTH    164            // output rows per CTA (492/3)
#define NT     256

// ---- smem layout ----------------------------------------------------------
#define ROWF   160            // padded row buffer floats
#define NBUF   6
#define OFF_ROW   0                           // 6*160*4   = 3840
#define OFF_WS    3840                        // 2*576*4   = 4608
#define OFF_HS    8448                        // 128*4     = 512
#define OFF_HQ    8960                        // 2*128*4   = 1024
#define OFF_HIST  9984                        // 21*128*8  = 21504
#define OFF_RING  31488                       // 21*256*8  = 43008
#define SMEM_TOTAL 74496

__device__ float g_Wh[PLANES][24 * 24];
__device__ float g_Wl[PLANES][24 * 24];

__device__ __forceinline__ uint32_t cvt_rna_tf32(float f) {
    uint32_t u;
    asm("cvt.rna.tf32.f32 %0, %1;" : "=r"(u) : "f"(f));
    return u;
}
__device__ __forceinline__ uint32_t smem_u32(const void* p) {
    uint32_t a;
    asm("{ .reg .u64 t; cvta.to.shared.u64 t, %1; cvt.u32.u64 %0, t; }"
        : "=r"(a) : "l"(p));
    return a;
}

#define MMA(c0,c1,c2,c3, a, b) \
    asm("mma.sync.aligned.m16n8k8.row.col.f32.tf32.tf32.f32 " \
        "{%0,%1,%2,%3}, {%4,%5,%6,%7}, {%8,%9}, {%0,%1,%2,%3};" \
        : "+f"(c0), "+f"(c1), "+f"(c2), "+f"(c3) \
        : "r"((a)[0]), "r"((a)[1]), "r"((a)[2]), "r"((a)[3]), \
          "r"((b)[0]), "r"((b)[1]))

#define CP_ASYNC16(dst, src) \
    asm volatile("cp.async.ca.shared.global [%0], [%1], 16;" \
                 :: "r"(dst), "l"(src) : "memory")
#define CP_COMMIT()  asm volatile("cp.async.commit_group;" ::: "memory")
#define CP_WAIT4()   asm volatile("cp.async.wait_group 4;" ::: "memory")

// ---------------------------------------------------------------------------
// Prep: z-normalize template planes -> padded 24x24 Wh (tf32-rna) / Wl tables.
// ---------------------------------------------------------------------------
__global__ void prep_template(const float* __restrict__ tmpl) {
    const int plane = blockIdx.x;
    const float* t = tmpl + plane * (TH * TH);
    __shared__ float s_t[TH * TH];
    __shared__ float s_sa[8], s_sb[8];
    __shared__ float s_mean, s_inv;

    int tid = threadIdx.x;
    float a = 0.f, b = 0.f;
    for (int i = tid; i < TH * TH; i += NT) {
        float v = t[i];
        s_t[i] = v; a += v; b += v * v;
    }
    #pragma unroll
    for (int o = 16; o; o >>= 1) {
        a += __shfl_xor_sync(0xffffffffu, a, o);
        b += __shfl_xor_sync(0xffffffffu, b, o);
    }
    if ((tid & 31) == 0) { s_sa[tid >> 5] = a; s_sb[tid >> 5] = b; }
    __syncthreads();
    if (tid == 0) {
        float sum = 0.f, sq = 0.f;
        #pragma unroll
        for (int i = 0; i < 8; i++) { sum += s_sa[i]; sq += s_sb[i]; }
        float mean = sum * (1.f / 441.f);
        float var  = fmaxf(sq * (1.f / 441.f) - mean * mean, 0.f);
        s_mean = mean;
        s_inv  = 1.f / ((sqrtf(var) + EPSF) * 441.f);
    }
    __syncthreads();

    const float mean = s_mean, inv = s_inv;
    for (int idx = tid; idx < 576; idx += NT) {
        int n = idx / 24, k = idx % 24;
        float wh = 0.f, wl = 0.f;
        if (n < 21 && k < 21) {
            float w = (s_t[n * 21 + k] - mean) * inv;
            wh = __uint_as_float(cvt_rna_tf32(w));
            wl = w - wh;
        } else if (n == 21 && k < 21) {
            wh = 1.f;               // ones column -> hsum
        }
        g_Wh[plane][idx] = wh;
        g_Wl[plane][idx] = wl;
    }
}

// ---------------------------------------------------------------------------
// Main kernel. Grid (4 x-strips, 3 y-thirds, 48 planes), 256 threads.
// ---------------------------------------------------------------------------
__global__ __launch_bounds__(NT, 2)
void ncc_tc(const float* __restrict__ inp, float* __restrict__ out) {
    extern __shared__ __align__(16) char sm[];
    float*  rowbuf = (float*)(sm + OFF_ROW);    // [6][160]
    float*  Wsm    = (float*)(sm + OFF_WS);     // [2][576]
    float*  hs     = (float*)(sm + OFF_HS);     // [128]
    float*  hq     = (float*)(sm + OFF_HQ);     // [2][128]
    float2* hist   = (float2*)(sm + OFF_HIST);  // [21][128]
    float2* ring   = (float2*)(sm + OFF_RING);  // [21][256]

    const int tid = threadIdx.x;
    const int l   = tid & 31;
    const int wid = tid >> 5;
    const int g   = l >> 2;
    const int t   = l & 3;
    const int woff = wid * 16;
    const int x1 = woff + g, x2 = x1 + 8;

    const int plane = blockIdx.z;
    const int x0 = blockIdx.x * XS;
    const int ys = blockIdx.y * YTH;
    const int yl = ys + YTH + 19;               // last input row consumed

    const float* pin = inp + (size_t)plane * (H * W);
    float* pout = out + (size_t)plane * (OH * OW);

    // ---- init: stage W, zero ring/hist/rowbuf ----
    for (int i = tid; i < 576; i += NT) {
        Wsm[i]       = g_Wh[plane][i];
        Wsm[576 + i] = g_Wl[plane][i];
    }
    {
        float2 z = make_float2(0.f, 0.f);
        for (int i = tid; i < 21 * 256; i += NT) ring[i] = z;
        for (int i = tid; i < 21 * 128; i += NT) hist[i] = z;
        for (int i = tid; i < NBUF * ROWF; i += NT) rowbuf[i] = 0.f;
    }
    __syncthreads();

    // ---- load B fragments (persistent in registers) ----
    uint32_t bh[3][3][2], bl[3][3][2];
    #pragma unroll
    for (int nb = 0; nb < 3; nb++)
        #pragma unroll
        for (int kb = 0; kb < 3; kb++) {
            int n = nb * 8 + g, k = kb * 8 + t;
            bh[nb][kb][0] = __float_as_uint(Wsm[n * 24 + k]);
            bh[nb][kb][1] = __float_as_uint(Wsm[n * 24 + k + 4]);
            bl[nb][kb][0] = __float_as_uint(Wsm[576 + n * 24 + k]);
            bl[nb][kb][1] = __float_as_uint(Wsm[576 + n * 24 + k + 4]);
        }

    // ---- cp.async prologue: rows ys..ys+4 into slots 0..4 ----
    const uint32_t rb_base = smem_u32(rowbuf);
    const bool loader = (tid < 38);
    const bool chunk_ok = loader && (x0 + 4 * tid + 3 < W);
    for (int r = 0; r < 5; r++) {
        if (loader) {
            if (chunk_ok)
                CP_ASYNC16(rb_base + r * (ROWF * 4) + tid * 16,
                           pin + (size_t)(ys + r) * W + x0 + 4 * tid);
            CP_COMMIT();
        }
    }

    float v1a = 0.f, v2a = 0.f, v1b = 0.f, v2b = 0.f;
    int basep = 0;            // (yin - ys) mod 21
    int rb = 0;               // (yin - ys) mod NBUF
    const float inv441 = 1.f / 441.f;

    #pragma unroll 1
    for (int yin = ys; yin <= ys + YTH + 20; yin++) {
        CP_WAIT4();
        __syncthreads();

        // ---- v-update (row yin-1's sums) + finalize y = yin-21 ----
        if (yin > ys) {
            if (t == 0) {
                int sp = basep - 1; if (sp < 0) sp = 20;
                float hsA = hs[x1], hsB = hs[x2];
                float hqA = hq[x1] + hq[128 + x1];
                float hqB = hq[x2] + hq[128 + x2];
                float2 hA = hist[sp * 128 + x1];
                float2 hB = hist[sp * 128 + x2];
                v1a += hsA - hA.x;  v2a += hqA - hA.y;
                v1b += hsB - hB.x;  v2b += hqB - hB.y;
                hist[sp * 128 + x1] = make_float2(hsA, hqA);
                hist[sp * 128 + x2] = make_float2(hsB, hqB);
            }
            if (yin >= ys + 21) {
                float2 pr = ring[basep * 256 + tid];
                ring[basep * 256 + tid] = make_float2(0.f, 0.f);
                float px = pr.x, py = pr.y;
                px += __shfl_xor_sync(0xffffffffu, px, 1);
                px += __shfl_xor_sync(0xffffffffu, px, 2);
                py += __shfl_xor_sync(0xffffffffu, py, 1);
                py += __shfl_xor_sync(0xffffffffu, py, 2);
                if (t == 0) {
                    int y = yin - 21;
                    float m1 = v1a * inv441, m2 = v2a * inv441;
                    float sd = sqrtf(m2 - m1 * m1 + EPSF);
                    int gx = x0 + x1;
                    if (gx < OW) pout[(size_t)y * OW + gx] = px / (sd + EPSF);
                    m1 = v1b * inv441; m2 = v2b * inv441;
                    sd = sqrtf(m2 - m1 * m1 + EPSF);
                    gx = x0 + x2;
                    if (gx < OW) pout[(size_t)y * OW + gx] = py / (sd + EPSF);
                }
            }
        }

        // Barrier: finalize reads of hs/hq must complete before this
        // iteration's GEMM overwrites them (WAR race fix).
        __syncthreads();

        // ---- GEMM row yin + staging + prefetch ----
        if (yin <= yl) {
            const float* bp = rowbuf + rb * ROWF;
            const int rel = yin - ys;          // max valid ring column index

            // A fragments (Toeplitz) + tf32 split
            uint32_t ah[3][4], al[3][4];
            #pragma unroll
            for (int kb = 0; kb < 3; kb++) {
                int bi = woff + g + kb * 8 + t;
                float a0 = bp[bi], a1 = bp[bi + 8], a2 = bp[bi + 4], a3 = bp[bi + 12];
                ah[kb][0] = cvt_rna_tf32(a0);
                ah[kb][1] = cvt_rna_tf32(a1);
                ah[kb][2] = cvt_rna_tf32(a2);
                ah[kb][3] = cvt_rna_tf32(a3);
                al[kb][0] = __float_as_uint(a0 - __uint_as_float(ah[kb][0]));
                al[kb][1] = __float_as_uint(a1 - __uint_as_float(ah[kb][1]));
                al[kb][2] = __float_as_uint(a2 - __uint_as_float(ah[kb][2]));
                al[kb][3] = __float_as_uint(a3 - __uint_as_float(ah[kb][3]));
            }

            #pragma unroll
            for (int nb = 0; nb < 3; nb++) {
                float c0 = 0.f, c1 = 0.f, c2 = 0.f, c3 = 0.f;
                #pragma unroll
                for (int kb = 0; kb < 3; kb++) MMA(c0, c1, c2, c3, ah[kb], bh[nb][kb]);
                #pragma unroll
                for (int kb = 0; kb < 3; kb++) MMA(c0, c1, c2, c3, al[kb], bh[nb][kb]);
                #pragma unroll
                for (int kb = 0; kb < 3; kb++) MMA(c0, c1, c2, c3, ah[kb], bl[nb][kb]);

                // ring accumulate: even col i0 = nb*8+2t, odd col i0+1.
                // Guard i0 <= rel: columns beyond yin-ys belong to outputs
                // above this CTA's range and would alias later ring slots.
                int i0 = nb * 8 + 2 * t;
                int se = basep - i0; se += (se < 0) ? 21 : 0; se += (se < 0) ? 21 : 0;
                int so = se - 1;     so += (so < 0) ? 21 : 0;
                if (i0 <= rel) {
                    float2 re = ring[se * 256 + tid];
                    re.x += c0; re.y += c2;
                    ring[se * 256 + tid] = re;
                }
                if (nb == 2 && t == 2) {       // odd col n=21 (ones) -> hsum
                    hs[x1] = c1; hs[x2] = c3;
                } else if (i0 + 1 <= rel) {
                    float2 ro = ring[so * 256 + tid];
                    ro.x += c1; ro.y += c3;
                    ring[so * 256 + tid] = ro;
                }
            }

            // hsq partial sums (taps 0..10 / 11..20 across thread halves)
            {
                int cq = tid & 127, hf = tid >> 7;
                const float* q = bp + cq + hf * 11;
                float s = 0.f;
                int cnt = 11 - hf;
                #pragma unroll 11
                for (int j = 0; j < cnt; j++) { float v = q[j]; s += v * v; }
                hq[hf * 128 + cq] = s;
            }

            // prefetch row yin+5 into slot (yin+5-ys) % NBUF
            if (loader) {
                int pr = yin + 5;
                if (pr <= yl && chunk_ok)
                    CP_ASYNC16(rb_base + ((pr - ys) % NBUF) * (ROWF * 4) + tid * 16,
                               pin + (size_t)pr * W + x0 + 4 * tid);
                CP_COMMIT();     // empty groups keep wait_group 4 discipline
            }
        }

        basep = (basep == 20) ? 0 : basep + 1;
        rb    = (rb == NBUF - 1) ? 0 : rb + 1;
    }
}

extern "C" void kernel_launch(void* const* d_in, const int* in_sizes, int n_in,
                              void* d_out, int out_size) {
    const float* inp  = (const float*)d_in[0];
    const float* tmpl = (const float*)d_in[1];
    if (n_in >= 2 && in_sizes[0] < in_sizes[1]) {
        const float* s = inp; inp = tmpl; tmpl = s;
    }
    cudaFuncSetAttribute(ncc_tc, cudaFuncAttributeMaxDynamicSharedMemorySize,
                         SMEM_TOTAL);
    prep_template<<<PLANES, NT>>>(tmpl);
    dim3 grid(4, 3, PLANES);     // x-strips, y-thirds, planes = 576 CTAs
    ncc_tc<<<grid, NT, SMEM_TOTAL>>>(inp, (float*)d_out);
}

// round 9
// speedup vs baseline: 2.7713x; 2.7713x over previous
#include <cuda_runtime.h>

// NCC: per-(b,c) 21x21 normalized cross-correlation, fp32.
// R9 = scalar f32x2 kernel, register-blocked 2 output rows per thread:
//   each input row (yb..yb+21) is loaded ONCE and feeds both output rows
//   (filter rows r and r-1) -> pixel LDS per FMA2 drops 1.9x.
// Bank stagger: odd row padding (41 chunks) + ((row>>1)&3) chunk shift gives
// conflict-free (4-phase) pixel LDS.128 without XOR swizzle.

#define EPSF    1e-8f
#define TH      21
#define PLANES  48
#define H       512
#define W       512
#define OH      492
#define OW      492
#define NPAIR   11
#define TILE_X  128          // 8 x-threads * 16 outputs
#define TILE_Y  32           // 16 y-groups * 2 rows
#define SROWS   (TILE_Y + 20)     // 52
#define NCHUNK  37                // 148 floats logical chunks
#define ROWCH   41                // padded chunks (odd) -> stagger room
#define ROWB    (ROWCH * 16)      // 656 B
#define NT      128

typedef unsigned long long ull;

__device__ ulonglong2 g_wEO[PLANES * TH * NPAIR];

__device__ __forceinline__ ull pack2(float a, float b) {
    ull r; asm("mov.b64 %0, {%1,%2};" : "=l"(r) : "f"(a), "f"(b)); return r;
}
__device__ __forceinline__ float lo2(ull v) { return __int_as_float((int)(v & 0xffffffffull)); }
__device__ __forceinline__ float hi2(ull v) { return __int_as_float((int)(v >> 32)); }

#define FMA2(acc, a, b) asm("fma.rn.f32x2 %0, %1, %2, %0;" : "+l"(acc) : "l"(a), "l"(b))

// smem layout (bytes)
#define OFF_W    0
#define SZ_W     (TH * NPAIR * 16)            // 3696
#define OFF_IN   3712
#define SZ_IN    (SROWS * ROWB)               // 34112
#define OFF_V1   (OFF_IN + SZ_IN)             // 37824
#define SZ_V     (TILE_Y * ROWB)              // 20992
#define OFF_V2   (OFF_V1 + SZ_V)              // 58816
#define SMEM_TOTAL (OFF_V2 + SZ_V)            // 79808

// ---------------------------------------------------------------------------
// Pass 0: normalize template planes, build interleaved packed weight table.
// ---------------------------------------------------------------------------
__global__ void prep_template(const float* __restrict__ tmpl) {
    const int plane = blockIdx.x;
    const float* t = tmpl + plane * (TH * TH);

    __shared__ float s_t[TH * TH];
    __shared__ float s_sa[4], s_sb[4];
    __shared__ float s_mean, s_inv;

    int tid = threadIdx.x;
    float a = 0.f, b = 0.f;
    for (int i = tid; i < TH * TH; i += NT) {
        float v = t[i];
        s_t[i] = v; a += v; b += v * v;
    }
    #pragma unroll
    for (int o = 16; o; o >>= 1) {
        a += __shfl_xor_sync(0xffffffffu, a, o);
        b += __shfl_xor_sync(0xffffffffu, b, o);
    }
    if ((tid & 31) == 0) { s_sa[tid >> 5] = a; s_sb[tid >> 5] = b; }
    __syncthreads();
    if (tid == 0) {
        float sum = s_sa[0] + s_sa[1] + s_sa[2] + s_sa[3];
        float sq  = s_sb[0] + s_sb[1] + s_sb[2] + s_sb[3];
        float mean = sum * (1.f / 441.f);
        float var  = fmaxf(sq * (1.f / 441.f) - mean * mean, 0.f);
        s_mean = mean;
        s_inv  = 1.f / ((sqrtf(var) + EPSF) * 441.f);
    }
    __syncthreads();

    const float mean = s_mean, inv = s_inv;
    for (int idx = tid; idx < TH * NPAIR; idx += NT) {
        int i  = idx / NPAIR;
        int tt = idx % NPAIR;
        int j0 = 2 * tt;
        float e0 = (s_t[i * TH + j0] - mean) * inv;
        float e1 = (j0 + 1 < TH) ? (s_t[i * TH + j0 + 1] - mean) * inv : 0.f;
        float o0 = (j0 - 1 >= 0) ? (s_t[i * TH + j0 - 1] - mean) * inv : 0.f;
        ulonglong2 w;
        w.x = pack2(e0, e1);   // even-based outputs
        w.y = pack2(o0, e0);   // odd-based outputs
        g_wEO[plane * TH * NPAIR + idx] = w;
    }
}

// stagger: physical chunk = logical chunk + ((row>>1) & 3)
__device__ __forceinline__ int rsh(int row) { return ((row >> 1) & 3) << 4; }

#define LOAD_PIX(buf, pp) do { \
    _Pragma("unroll") \
    for (int _u = 0; _u < 9; _u++) { \
        ulonglong2 _q = *(const ulonglong2*)((pp) + _u * 16); \
        (buf)[2 * _u] = _q.x; (buf)[2 * _u + 1] = _q.y; \
    } \
} while (0)

#define FMA_TWO(pb, wa, wb) do { \
    _Pragma("unroll") \
    for (int _g = 0; _g < 8; _g++) { \
        FMA2(accA[2 * _g],     (pb)[_g], (wa).x); \
        FMA2(accA[2 * _g + 1], (pb)[_g], (wa).y); \
        FMA2(accB[2 * _g],     (pb)[_g], (wb).x); \
        FMA2(accB[2 * _g + 1], (pb)[_g], (wb).y); \
    } \
} while (0)

// ---------------------------------------------------------------------------
// Main. Block = 128x32 tile; thread = 2 rows x 16 consecutive cols. 128 thr.
// ---------------------------------------------------------------------------
__global__ __launch_bounds__(NT, 2)
void ncc_main(const float* __restrict__ inp, float* __restrict__ out) {
    extern __shared__ __align__(16) char dynsmem[];
    ulonglong2* s_wEO = (ulonglong2*)(dynsmem + OFF_W);
    char* s_in  = dynsmem + OFF_IN;
    char* s_v1  = dynsmem + OFF_V1;
    char* s_v2  = dynsmem + OFF_V2;

    const int plane = blockIdx.z;
    const int x0 = blockIdx.x * TILE_X;
    const int y0 = blockIdx.y * TILE_Y;
    const int tid = threadIdx.x;

    const float* pin = inp + (size_t)plane * (H * W);

    // Tile load with stagger.
    for (int g = tid; g < SROWS * NCHUNK; g += NT) {
        int r = g / NCHUNK;
        int c = g - r * NCHUNK;
        int gy = y0 + r, gx = x0 + 4 * c;
        float4 v = make_float4(0.f, 0.f, 0.f, 0.f);
        if (gy < H && gx < W) v = *(const float4*)(pin + (size_t)gy * W + gx);
        *(float4*)(s_in + r * ROWB + c * 16 + rsh(r)) = v;
    }
    for (int idx = tid; idx < TH * NPAIR; idx += NT)
        s_wEO[idx] = g_wEO[plane * TH * NPAIR + idx];
    __syncthreads();

    const int xt  = tid & 7;        // x-group (16 outputs)
    const int ytg = tid >> 3;       // y-group (2 rows)
    const int yb  = 2 * ytg;
    const int cb16 = (4 * xt) * 16; // base chunk byte offset

    ull accA[16], accB[16];
    #pragma unroll
    for (int m = 0; m < 16; m++) { accA[m] = 0ull; accB[m] = 0ull; }

    ull p[18];
    // r = 0: row yb feeds accA (filter row 0)
    {
        const char* pp = s_in + yb * ROWB + rsh(yb) + cb16;
        LOAD_PIX(p, pp);
        #pragma unroll
        for (int t = 0; t < NPAIR; t++) {
            ulonglong2 wa = s_wEO[t];
            #pragma unroll
            for (int g = 0; g < 8; g++) {
                FMA2(accA[2 * g],     p[g + t], wa.x);
                FMA2(accA[2 * g + 1], p[g + t], wa.y);
            }
        }
    }
    // r = 1..20: row yb+r feeds accA (row r) and accB (row r-1)
    #pragma unroll 2
    for (int r = 1; r <= 20; r++) {
        const int row = yb + r;
        const char* pp = s_in + row * ROWB + rsh(row) + cb16;
        LOAD_PIX(p, pp);
        #pragma unroll
        for (int t = 0; t < NPAIR; t++) {
            ulonglong2 wa = s_wEO[r * NPAIR + t];
            ulonglong2 wb = s_wEO[(r - 1) * NPAIR + t];
            FMA_TWO(p + t, wa, wb);
        }
    }
    // r = 21: row yb+21 feeds accB (filter row 20)
    {
        const int row = yb + 21;
        const char* pp = s_in + row * ROWB + rsh(row) + cb16;
        LOAD_PIX(p, pp);
        #pragma unroll
        for (int t = 0; t < NPAIR; t++) {
            ulonglong2 wb = s_wEO[20 * NPAIR + t];
            #pragma unroll
            for (int g = 0; g < 8; g++) {
                FMA2(accB[2 * g],     p[g + t], wb.x);
                FMA2(accB[2 * g + 1], p[g + t], wb.y);
            }
        }
    }

    // Vertical sliding box sums (columns strided across 128 threads).
    for (int c = tid; c < 148; c += NT) {
        const int cb4 = (c >> 2) * 16 + (c & 3) * 4;
        float s1 = 0.f, s2 = 0.f;
        #pragma unroll
        for (int r = 0; r < TH; r++) {
            float v = *(const float*)(s_in + r * ROWB + rsh(r) + cb4);
            s1 += v; s2 += v * v;
        }
        *(float*)(s_v1 + cb4) = s1;
        *(float*)(s_v2 + cb4) = s2;
        for (int y = 1; y < TILE_Y; y++) {
            float va = *(const float*)(s_in + (y + 20) * ROWB + rsh(y + 20) + cb4);
            float vr = *(const float*)(s_in + (y - 1) * ROWB + rsh(y - 1) + cb4);
            s1 += va - vr;
            s2 += va * va - vr * vr;
            *(float*)(s_v1 + y * ROWB + cb4) = s1;
            *(float*)(s_v2 + y * ROWB + cb4) = s2;
        }
    }
    __syncthreads();

    // Epilogue (both output rows): horizontal box sums + normalize + store.
    const float inv441 = 1.f / 441.f;
    float* pbase = out + (size_t)plane * (OH * OW);
    const int oxb = x0 + 16 * xt;

    #pragma unroll
    for (int rr = 0; rr < 2; rr++) {
        const int yrow = yb + rr;
        const ull* acc = rr ? accB : accA;

        float num[16];
        #pragma unroll
        for (int m = 0; m < 16; m++) num[m] = lo2(acc[m]) + hi2(acc[m]);

        float h1[16], h2[16];
        {
            float V[36];
            #pragma unroll
            for (int u = 0; u < 9; u++) {
                float4 q = *(const float4*)(s_v1 + yrow * ROWB + cb16 + u * 16);
                V[4*u] = q.x; V[4*u+1] = q.y; V[4*u+2] = q.z; V[4*u+3] = q.w;
            }
            float h = 0.f;
            #pragma unroll
            for (int k = 0; k < TH; k++) h += V[k];
            h1[0] = h;
            #pragma unroll
            for (int m = 1; m < 16; m++) { h += V[m + 20] - V[m - 1]; h1[m] = h; }
        }
        {
            float V[36];
            #pragma unroll
            for (int u = 0; u < 9; u++) {
                float4 q = *(const float4*)(s_v2 + yrow * ROWB + cb16 + u * 16);
                V[4*u] = q.x; V[4*u+1] = q.y; V[4*u+2] = q.z; V[4*u+3] = q.w;
            }
            float h = 0.f;
            #pragma unroll
            for (int k = 0; k < TH; k++) h += V[k];
            h2[0] = h;
            #pragma unroll
            for (int m = 1; m < 16; m++) { h += V[m + 20] - V[m - 1]; h2[m] = h; }
        }

        const int oy = y0 + yrow;
        if (oy < OH) {
            float* prow = pbase + (size_t)oy * OW;
            #pragma unroll
            for (int q4 = 0; q4 < 4; q4++) {
                int ox = oxb + 4 * q4;
                if (ox + 3 < OW) {
                    float4 o;
                    float* po = &o.x;
                    #pragma unroll
                    for (int e = 0; e < 4; e++) {
                        int m = 4 * q4 + e;
                        float mean = h1[m] * inv441;
                        float msq  = h2[m] * inv441;
                        float stdv = sqrtf(msq - mean * mean + EPSF);
                        po[e] = num[m] / (stdv + EPSF);
                    }
                    *(float4*)(prow + ox) = o;
                }
            }
        }
    }
}

extern "C" void kernel_launch(void* const* d_in, const int* in_sizes, int n_in,
                              void* d_out, int out_size) {
    const float* inp  = (const float*)d_in[0];
    const float* tmpl = (const float*)d_in[1];
    if (n_in >= 2 && in_sizes[0] < in_sizes[1]) {
        const float* t = inp; inp = tmpl; tmpl = t;
    }
    cudaFuncSetAttribute(ncc_main, cudaFuncAttributeMaxDynamicSharedMemorySize,
                         SMEM_TOTAL);
    prep_template<<<PLANES, NT>>>(tmpl);
    dim3 grid((OW + TILE_X - 1) / TILE_X,   // 4
              (OH + TILE_Y - 1) / TILE_Y,   // 16
              PLANES);                      // 48
    ncc_main<<<grid, NT, SMEM_TOTAL>>>(inp, (float*)d_out);
}

// round 10
// speedup vs baseline: 3.4219x; 1.2347x over previous
#include <cuda_runtime.h>

// NCC: per-(b,c) 21x21 normalized cross-correlation, fp32.
// R10 = R6 (validated, 256.5us) + reuse-friendly FMA ordering:
//   inner loop split into even-parity pass (b-operand = w.x constant x8) and
//   odd-parity pass (b = w.y constant x8). Constant b-slot across consecutive
//   FFMA2s lets ptxas .reuse the operand -> 2 distinct regs/bank (rt 2) vs 3.
//   FMA2 asm made volatile to preserve the adjacency through nvcc.

#define EPSF    1e-8f
#define TH      21
#define PLANES  48
#define H       512
#define W       512
#define OH      492
#define OW      492
#define NPAIR   11
#define TILE_X  128          // 8 x-threads * 16 outputs
#define TILE_Y  32           // 32 y-threads * 1 row
#define SROWS   (TILE_Y + 20)     // 52
#define NCHUNK  37                // 148 floats = 37 16B-chunks (logical)
#define ROWCH   40                // padded physical chunks per row
#define ROWB    (ROWCH * 16)      // 640 B row stride
#define NTHREADS 256

typedef unsigned long long ull;

// interleaved packed weight table: [plane][filter_row][pair] = (wE, wO)
__device__ ulonglong2 g_wEO[PLANES * TH * NPAIR];

__device__ __forceinline__ ull pack2(float a, float b) {
    ull r; asm("mov.b64 %0, {%1,%2};" : "=l"(r) : "f"(a), "f"(b)); return r;
}
__device__ __forceinline__ float lo2(ull v) { return __int_as_float((int)(v & 0xffffffffull)); }
__device__ __forceinline__ float hi2(ull v) { return __int_as_float((int)(v >> 32)); }

// volatile: keep issue order so consecutive FMA2s share the b-operand slot
#define FMA2V(acc, a, b) \
    asm volatile("fma.rn.f32x2 %0, %1, %2, %0;" : "+l"(acc) : "l"(a), "l"(b))

// XOR swizzle on 16B-chunk index (keeps chunks inside their 128B segment)
__device__ __forceinline__ int swz(int c) { return c ^ ((c >> 3) & 7); }

// smem layout (bytes)
#define OFF_W    0
#define SZ_W     (TH * NPAIR * 16)            // 3696
#define OFF_IN   3712                          // 16B aligned
#define SZ_IN    (SROWS * ROWB)                // 33280
#define OFF_V1   (OFF_IN + SZ_IN)              // 36992
#define SZ_V     (TILE_Y * ROWB)               // 20480
#define OFF_V2   (OFF_V1 + SZ_V)               // 57472
#define SMEM_TOTAL (OFF_V2 + SZ_V)             // 77952

// ---------------------------------------------------------------------------
// Pass 0: normalize template planes, build interleaved packed weight table.
// ---------------------------------------------------------------------------
__global__ void prep_template(const float* __restrict__ tmpl) {
    const int plane = blockIdx.x;
    const float* t = tmpl + plane * (TH * TH);

    __shared__ float s_t[TH * TH];
    __shared__ float s_sa[8], s_sb[8];
    __shared__ float s_mean, s_inv;

    int tid = threadIdx.x;
    float a = 0.f, b = 0.f;
    for (int i = tid; i < TH * TH; i += NTHREADS) {
        float v = t[i];
        s_t[i] = v;
        a += v; b += v * v;
    }
    #pragma unroll
    for (int o = 16; o; o >>= 1) {
        a += __shfl_xor_sync(0xffffffffu, a, o);
        b += __shfl_xor_sync(0xffffffffu, b, o);
    }
    if ((tid & 31) == 0) { s_sa[tid >> 5] = a; s_sb[tid >> 5] = b; }
    __syncthreads();
    if (tid == 0) {
        float sum = 0.f, sq = 0.f;
        #pragma unroll
        for (int wdx = 0; wdx < 8; wdx++) { sum += s_sa[wdx]; sq += s_sb[wdx]; }
        float mean = sum * (1.f / 441.f);
        float var  = fmaxf(sq * (1.f / 441.f) - mean * mean, 0.f);
        s_mean = mean;
        s_inv  = 1.f / ((sqrtf(var) + EPSF) * 441.f);
    }
    __syncthreads();

    const float mean = s_mean, inv = s_inv;
    for (int idx = tid; idx < TH * NPAIR; idx += NTHREADS) {
        int i  = idx / NPAIR;
        int tt = idx % NPAIR;
        int j0 = 2 * tt;
        float e0 = (s_t[i * TH + j0] - mean) * inv;
        float e1 = (j0 + 1 < TH) ? (s_t[i * TH + j0 + 1] - mean) * inv : 0.f;
        float o0 = (j0 - 1 >= 0) ? (s_t[i * TH + j0 - 1] - mean) * inv : 0.f;
        ulonglong2 w;
        w.x = pack2(e0, e1);   // even-based outputs
        w.y = pack2(o0, e0);   // odd-based outputs
        g_wEO[plane * TH * NPAIR + idx] = w;
    }
}

// helper macros for the mainloop --------------------------------------------
#define LOAD_PIX(buf, rowptr) do { \
    _Pragma("unroll") \
    for (int _u = 0; _u < 9; _u++) { \
        ulonglong2 _q = *(const ulonglong2*)((rowptr) + coff[_u]); \
        (buf)[2 * _u] = _q.x; (buf)[2 * _u + 1] = _q.y; \
    } \
} while (0)

#define LOAD_W(wbuf, i) do { \
    _Pragma("unroll") \
    for (int _t = 0; _t < NPAIR; _t++) (wbuf)[_t] = s_wEO[(i) * NPAIR + _t]; \
} while (0)

// parity-split: even pass (b = w.x constant), then odd pass (b = w.y constant)
#define FMA_ROW(buf, wbuf) do { \
    _Pragma("unroll") \
    for (int _t = 0; _t < NPAIR; _t++) { \
        _Pragma("unroll") \
        for (int _g = 0; _g < 8; _g++) \
            FMA2V(acc[2 * _g], (buf)[_g + _t], (wbuf)[_t].x); \
        _Pragma("unroll") \
        for (int _g = 0; _g < 8; _g++) \
            FMA2V(acc[2 * _g + 1], (buf)[_g + _t], (wbuf)[_t].y); \
    } \
} while (0)

// ---------------------------------------------------------------------------
// Pass 1: main NCC. Block = 128x32 tile; thread = 1 row x 16 consecutive cols.
// ---------------------------------------------------------------------------
__global__ __launch_bounds__(NTHREADS, 2)
void ncc_main(const float* __restrict__ inp, float* __restrict__ out) {
    extern __shared__ __align__(16) char dynsmem[];
    ulonglong2* s_wEO = (ulonglong2*)(dynsmem + OFF_W);
    char* s_in  = dynsmem + OFF_IN;
    char* s_v1  = dynsmem + OFF_V1;
    char* s_v2  = dynsmem + OFF_V2;

    const int plane = blockIdx.z;
    const int x0 = blockIdx.x * TILE_X;
    const int y0 = blockIdx.y * TILE_Y;
    const int tid = threadIdx.x;

    const float* pin = inp + (size_t)plane * (H * W);

    // Load input tile: 52 rows x 37 logical chunks, swizzled placement.
    for (int g = tid; g < SROWS * NCHUNK; g += NTHREADS) {
        int r = g / NCHUNK;
        int c = g - r * NCHUNK;              // logical 16B chunk
        int gy = y0 + r, gx = x0 + 4 * c;
        float4 v = make_float4(0.f, 0.f, 0.f, 0.f);
        if (gy < H && gx < W) v = *(const float4*)(pin + (size_t)gy * W + gx);
        *(float4*)(s_in + r * ROWB + swz(c) * 16) = v;
    }
    for (int idx = tid; idx < TH * NPAIR; idx += NTHREADS)
        s_wEO[idx] = g_wEO[plane * TH * NPAIR + idx];
    __syncthreads();

    const int xt = tid & 7;        // 16-output column group
    const int yt = tid >> 3;       // output row within tile

    // Precomputed swizzled byte offsets for this thread's 9 pixel chunks.
    int coff[9];
    #pragma unroll
    for (int u = 0; u < 9; u++) coff[u] = swz(4 * xt + u) * 16;

    ull acc[16];
    #pragma unroll
    for (int m = 0; m < 16; m++) acc[m] = 0ull;

    // ---- software-pipelined mainloop: 21 filter rows --------------------
    const char* base = s_in + yt * ROWB;
    ull p[18], q[18];
    ulonglong2 w[NPAIR];

    LOAD_PIX(p, base);                         // row 0
    #pragma unroll 1
    for (int i = 0; i < 20; i += 2) {
        LOAD_W(w, i);
        LOAD_PIX(q, base + (i + 1) * ROWB);    // prefetch row i+1
        FMA_ROW(p, w);                         // row i
        LOAD_W(w, i + 1);
        LOAD_PIX(p, base + (i + 2) * ROWB);    // prefetch row i+2 (<= 20)
        FMA_ROW(q, w);                         // row i+1
    }
    LOAD_W(w, 20);
    FMA_ROW(p, w);                             // row 20

    // Vertical sliding box sums of x, x^2 (threads 0..147, one column each),
    // written swizzled so the epilogue can vector-load them.
    if (tid < 148) {
        const int c = tid;
        const int colb = swz(c >> 2) * 16 + (c & 3) * 4;   // swizzled byte off
        float s1 = 0.f, s2 = 0.f;
        #pragma unroll
        for (int r = 0; r < TH; r++) {
            float v = *(const float*)(s_in + r * ROWB + colb);
            s1 += v; s2 += v * v;
        }
        *(float*)(s_v1 + colb) = s1;
        *(float*)(s_v2 + colb) = s2;
        for (int y = 1; y < TILE_Y; y++) {
            float va = *(const float*)(s_in + (y + 20) * ROWB + colb);
            float vr = *(const float*)(s_in + (y - 1) * ROWB + colb);
            s1 += va - vr;
            s2 += va * va - vr * vr;
            *(float*)(s_v1 + y * ROWB + colb) = s1;
            *(float*)(s_v2 + y * ROWB + colb) = s2;
        }
    }
    __syncthreads();

    // Epilogue: reduce packed accumulators, register-resident horizontal sums.
    float num[16];
    #pragma unroll
    for (int m = 0; m < 16; m++) num[m] = lo2(acc[m]) + hi2(acc[m]);

    float h1[16], h2[16];
    {
        float V[36];
        #pragma unroll
        for (int u = 0; u < 9; u++) {
            float4 qv = *(const float4*)(s_v1 + yt * ROWB + coff[u]);
            V[4*u] = qv.x; V[4*u+1] = qv.y; V[4*u+2] = qv.z; V[4*u+3] = qv.w;
        }
        float h = 0.f;
        #pragma unroll
        for (int k = 0; k < TH; k++) h += V[k];
        h1[0] = h;
        #pragma unroll
        for (int m = 1; m < 16; m++) { h += V[m + 20] - V[m - 1]; h1[m] = h; }
    }
    {
        float V[36];
        #pragma unroll
        for (int u = 0; u < 9; u++) {
            float4 qv = *(const float4*)(s_v2 + yt * ROWB + coff[u]);
            V[4*u] = qv.x; V[4*u+1] = qv.y; V[4*u+2] = qv.z; V[4*u+3] = qv.w;
        }
        float h = 0.f;
        #pragma unroll
        for (int k = 0; k < TH; k++) h += V[k];
        h2[0] = h;
        #pragma unroll
        for (int m = 1; m < 16; m++) { h += V[m + 20] - V[m - 1]; h2[m] = h; }
    }

    const float inv441 = 1.f / 441.f;
    const int oy = y0 + yt;
    const int oxb = x0 + 16 * xt;
    if (oy < OH) {
        float* prow = out + (size_t)plane * (OH * OW) + (size_t)oy * OW;
        #pragma unroll
        for (int q4 = 0; q4 < 4; q4++) {
            int ox = oxb + 4 * q4;
            if (ox + 3 < OW) {                 // OW divisible by 4, ox 4-aligned
                float4 o;
                float* po = &o.x;
                #pragma unroll
                for (int e = 0; e < 4; e++) {
                    int m = 4 * q4 + e;
                    float mean = h1[m] * inv441;
                    float msq  = h2[m] * inv441;
                    float stdv = sqrtf(msq - mean * mean + EPSF);
                    po[e] = num[m] / (stdv + EPSF);
                }
                *(float4*)(prow + ox) = o;
            }
        }
    }
}

extern "C" void kernel_launch(void* const* d_in, const int* in_sizes, int n_in,
                              void* d_out, int out_size) {
    const float* inp  = (const float*)d_in[0];
    const float* tmpl = (const float*)d_in[1];
    if (n_in >= 2 && in_sizes[0] < in_sizes[1]) {
        const float* t = inp; inp = tmpl; tmpl = t;
    }
    cudaFuncSetAttribute(ncc_main, cudaFuncAttributeMaxDynamicSharedMemorySize,
                         SMEM_TOTAL);
    prep_template<<<PLANES, NTHREADS>>>(tmpl);
    dim3 grid((OW + TILE_X - 1) / TILE_X,   // 4
              (OH + TILE_Y - 1) / TILE_Y,   // 16
              PLANES);                      // 48
    ncc_main<<<grid, NTHREADS, SMEM_TOTAL>>>(inp, (float*)d_out);
}